// round 2
// baseline (speedup 1.0000x reference)
#include <cuda_runtime.h>
#include <math.h>

#define Bx 32
#define Tx 128
#define Hx 256
#define Mx 1000
#define Qx 4
#define TILE_M 8
#define NTILES 125   // 1000 / 8

// ------------------------- device scratch -------------------------
__device__ float gH [Bx*Tx*Hx];          // h = (x@proj_w + b) * valid   (4 MB)
__device__ float gHC[Bx*Tx*8];           // conv-block output (silu(ln(conv)))*valid
__device__ float gE [Bx*Tx];             // cumsum end times
__device__ float gS [Bx*Tx];             // start times
__device__ int   gML[Bx];                // mel_lens
__device__ float gY [(size_t)Bx*Qx*Tx*Hx]; // Y[b,q,t,o] = x[b,t,:]@proj1_w[q*H+:, o]  (16 MB)

// ------------------------- kDur: cumsum + mel_lens -------------------------
__global__ void kDur(const float* __restrict__ xdur, float* __restrict__ outLens) {
    int b = blockIdx.x;
    if (threadIdx.x == 0) {
        float run = 0.f;
        for (int t = 0; t < Tx; t++) {
            float d = xdur[b*Tx + t];
            gS[b*Tx + t] = run;
            run += d;
            gE[b*Tx + t] = run;
        }
        int ml = (int)rintf(run);      // round-half-even, matches jnp.round
        if (ml > Mx) ml = Mx;
        gML[b] = ml;
        outLens[b] = (float)ml;
    }
}

// ------------------------- kH: h = (x@proj_w + b)*valid -------------------------
__global__ void __launch_bounds__(Hx) kH(const float* __restrict__ x,
                                         const float* __restrict__ pw,
                                         const float* __restrict__ pb,
                                         const int*   __restrict__ xlens) {
    __shared__ float xs[8][Hx];
    int r0 = blockIdx.x * 8;          // global row = b*T + t
    int tid = threadIdx.x;
    #pragma unroll
    for (int i = 0; i < 8; i++) xs[i][tid] = x[(size_t)(r0+i)*Hx + tid];
    __syncthreads();
    float bias = pb[tid];
    float acc[8];
    #pragma unroll
    for (int i = 0; i < 8; i++) acc[i] = bias;
    for (int h = 0; h < Hx; h++) {
        float w = pw[h*Hx + tid];
        #pragma unroll
        for (int i = 0; i < 8; i++) acc[i] = fmaf(xs[i][h], w, acc[i]);
    }
    int b = r0 / Tx;
    int xlen = xlens[b];
    #pragma unroll
    for (int i = 0; i < 8; i++) {
        int t = (r0 + i) & (Tx - 1);
        gH[(size_t)(r0+i)*Hx + tid] = (t < xlen) ? acc[i] : 0.f;
    }
}

// ------------------------- kConv: conv1d(k=3) + LN(8) + silu, *valid -------------------------
__global__ void __launch_bounds__(Hx) kConv(const float* __restrict__ cw,
                                            const float* __restrict__ cb,
                                            const float* __restrict__ cg,
                                            const float* __restrict__ cbeta,
                                            const int*   __restrict__ xlens) {
    int bt = blockIdx.x;
    int b = bt >> 7, t = bt & 127;
    int cin = threadIdx.x;

    float hm = (t > 0)   ? gH[(size_t)(bt-1)*Hx + cin] : 0.f;
    float h0 =             gH[(size_t) bt   *Hx + cin];
    float hp = (t < 127) ? gH[(size_t)(bt+1)*Hx + cin] : 0.f;

    float loc[8];
    #pragma unroll
    for (int c = 0; c < 8; c++) {
        const float* w = cw + c*(Hx*3) + cin*3;
        loc[c] = fmaf(w[0], hm, fmaf(w[1], h0, w[2]*hp));
    }
    #pragma unroll
    for (int off = 16; off > 0; off >>= 1) {
        #pragma unroll
        for (int c = 0; c < 8; c++)
            loc[c] += __shfl_xor_sync(0xffffffffu, loc[c], off);
    }
    __shared__ float red[8][8];
    __shared__ float tmp8[8];
    int warp = cin >> 5, lane = cin & 31;
    if (lane == 0) {
        #pragma unroll
        for (int c = 0; c < 8; c++) red[warp][c] = loc[c];
    }
    __syncthreads();
    if (cin < 8) {
        float v = cb[cin];
        #pragma unroll
        for (int w = 0; w < 8; w++) v += red[w][cin];
        tmp8[cin] = v;
    }
    __syncthreads();
    if (cin < 8) {
        float mu = 0.f;
        #pragma unroll
        for (int j = 0; j < 8; j++) mu += tmp8[j];
        mu *= 0.125f;
        float var = 0.f;
        #pragma unroll
        for (int j = 0; j < 8; j++) { float d = tmp8[j]-mu; var = fmaf(d, d, var); }
        var *= 0.125f;
        float zn = (tmp8[cin]-mu) * rsqrtf(var + 1e-5f) * cg[cin] + cbeta[cin];
        float sil = zn / (1.f + expf(-zn));
        gHC[bt*8 + cin] = (t < xlens[b]) ? sil : 0.f;
    }
}

// ------------------------- kY: Y[b,q,t,o] = x[b,t,:] @ proj1_w[q*H+:, o] -------------------------
__global__ void __launch_bounds__(Hx) kY(const float* __restrict__ x,
                                         const float* __restrict__ p1w) {
    int blk = blockIdx.x;                 // b*32 + q*8 + tile
    int tile = blk & 7;
    int q    = (blk >> 3) & 3;
    int b    = blk >> 5;
    int t0   = tile * 16;
    __shared__ float xs[16][Hx];
    int tid = threadIdx.x;
    #pragma unroll
    for (int i = 0; i < 16; i++) xs[i][tid] = x[(size_t)(b*Tx + t0 + i)*Hx + tid];
    __syncthreads();
    float acc[16];
    #pragma unroll
    for (int i = 0; i < 16; i++) acc[i] = 0.f;
    for (int h = 0; h < Hx; h++) {
        float w = p1w[(size_t)(q*Hx + h)*Hx + tid];
        #pragma unroll
        for (int i = 0; i < 16; i++) acc[i] = fmaf(xs[i][h], w, acc[i]);
    }
    #pragma unroll
    for (int i = 0; i < 16; i++)
        gY[(size_t)((b*Qx + q)*Tx + t0 + i)*Hx + tid] = acc[i];
}

// ------------------------- kMain: fused per (b, 8-m tile) -------------------------
__global__ void __launch_bounds__(128) kMain(
    const int*   __restrict__ xlens,
    const float* __restrict__ qw1, const float* __restrict__ qb1,
    const float* __restrict__ qg,  const float* __restrict__ qbeta,
    const float* __restrict__ qw2, const float* __restrict__ qb2,
    const float* __restrict__ pw1, const float* __restrict__ pb1,
    const float* __restrict__ pg,  const float* __restrict__ pbeta,
    const float* __restrict__ pw2, const float* __restrict__ pb2,
    const float* __restrict__ p1b, const float* __restrict__ p2w,
    const float* __restrict__ p2b, const float* __restrict__ pow_,
    const float* __restrict__ pob,
    float* __restrict__ outO, float* __restrict__ outMask,
    float* __restrict__ outW)
{
    __shared__ float hc_sh[Tx][9];
    __shared__ float sE[Tx], sS[Tx];
    __shared__ float w_sh[TILE_M][Tx][4];
    __shared__ float u_sh[TILE_M][Hx];
    __shared__ float wc_sh[TILE_M][8];
    __shared__ float redA[4][4];
    __shared__ float redB[4][4];
    __shared__ float redC[4][8];

    int b    = blockIdx.x / NTILES;
    int tile = blockIdx.x % NTILES;
    int m0   = tile * TILE_M;
    int t    = threadIdx.x;
    int warp = t >> 5, lane = t & 31;
    int mel_len = gML[b];
    int xlen    = xlens[b];

    // -------- fully padded tile fast path --------
    if (m0 >= mel_len) {
        #pragma unroll
        for (int mi = 0; mi < TILE_M; mi++) {
            int m = m0 + mi;
            outMask[(size_t)(b*Mx + m)*Tx + t] = 1.f;
            #pragma unroll
            for (int q = 0; q < 4; q++)
                outW[((size_t)(b*Qx + q)*Mx + m)*Tx + t] = 0.f;
            float* op = outO + (size_t)(b*Mx + m)*(2*Hx);
            #pragma unroll
            for (int r = 0; r < 4; r++) { int j = t + r*128; op[j] = pob[j]; }
        }
        return;
    }

    // -------- shared loads --------
    #pragma unroll
    for (int c = 0; c < 8; c++) hc_sh[t][c] = gHC[(b*Tx + t)*8 + c];
    sE[t] = gE[b*Tx + t];
    sS[t] = gS[b*Tx + t];
    __syncthreads();

    bool tmask = (t >= xlen);
    float fh[8];
    #pragma unroll
    for (int c = 0; c < 8; c++) fh[c] = hc_sh[t][c];
    float se = sE[t], ss = sS[t];

    // precompute m-independent parts of the two tiny MLPs
    float zqb[4];
    #pragma unroll
    for (int q = 0; q < 4; q++) zqb[q] = qb1[q];
    #pragma unroll
    for (int i = 0; i < 8; i++) {
        #pragma unroll
        for (int q = 0; q < 4; q++) zqb[q] = fmaf(fh[i], qw1[i*4 + q], zqb[q]);
    }
    float zpb0 = pb1[0], zpb1 = pb1[1];
    #pragma unroll
    for (int i = 0; i < 8; i++) {
        zpb0 = fmaf(fh[i], pw1[i*2 + 0], zpb0);
        zpb1 = fmaf(fh[i], pw1[i*2 + 1], zpb1);
    }

    // -------- phase 1: per-m scores, softmax, wc --------
    for (int mi = 0; mi < TILE_M; mi++) {
        int m = m0 + mi;
        bool pad = (m >= mel_len);
        outMask[(size_t)(b*Mx + m)*Tx + t] = pad ? 1.f : 0.f;
        if (pad) {
            #pragma unroll
            for (int q = 0; q < 4; q++) {
                w_sh[mi][t][q] = 0.f;
                outW[((size_t)(b*Qx + q)*Mx + m)*Tx + t] = 0.f;
            }
            if (t < 8) wc_sh[mi][t] = 0.f;
            continue;
        }
        float tf = (float)(m + 1);
        float f8 = tmask ? 0.f : (tf - ss);
        float f9 = tmask ? 0.f : (se - tf);

        // q-MLP
        float z[4];
        #pragma unroll
        for (int q = 0; q < 4; q++)
            z[q] = fmaf(f9, qw1[36 + q], fmaf(f8, qw1[32 + q], zqb[q]));
        float mu = 0.25f * (z[0] + z[1] + z[2] + z[3]);
        float var = 0.f;
        #pragma unroll
        for (int q = 0; q < 4; q++) { float d = z[q]-mu; var = fmaf(d, d, var); }
        var *= 0.25f;
        float rinv = rsqrtf(var + 1e-5f);
        float a[4];
        #pragma unroll
        for (int q = 0; q < 4; q++) {
            float zn = (z[q]-mu) * rinv * qg[q] + qbeta[q];
            a[q] = zn / (1.f + expf(-zn));
        }
        float sc[4];
        #pragma unroll
        for (int q = 0; q < 4; q++) {
            float s = qb2[q];
            #pragma unroll
            for (int j = 0; j < 4; j++) s = fmaf(a[j], qw2[j*4 + q], s);
            sc[q] = tmask ? -1e30f : s;
        }

        // p-MLP
        float zp0 = fmaf(f9, pw1[18], fmaf(f8, pw1[16], zpb0));
        float zp1 = fmaf(f9, pw1[19], fmaf(f8, pw1[17], zpb1));
        float mup  = 0.5f * (zp0 + zp1);
        float d0 = zp0 - mup, d1 = zp1 - mup;
        float varp = 0.5f * (d0*d0 + d1*d1);
        float rp = rsqrtf(varp + 1e-5f);
        float a0 = d0 * rp * pg[0] + pbeta[0];
        float a1 = d1 * rp * pg[1] + pbeta[1];
        a0 = a0 / (1.f + expf(-a0));
        a1 = a1 / (1.f + expf(-a1));
        float c0 = fmaf(a1, pw2[2], fmaf(a0, pw2[0], pb2[0]));
        float c1 = fmaf(a1, pw2[3], fmaf(a0, pw2[1], pb2[1]));

        // block softmax over t, 4 q's at once
        float v[4];
        #pragma unroll
        for (int q = 0; q < 4; q++) v[q] = sc[q];
        #pragma unroll
        for (int off = 16; off > 0; off >>= 1) {
            #pragma unroll
            for (int q = 0; q < 4; q++)
                v[q] = fmaxf(v[q], __shfl_xor_sync(0xffffffffu, v[q], off));
        }
        if (lane == 0) {
            #pragma unroll
            for (int q = 0; q < 4; q++) redA[warp][q] = v[q];
        }
        __syncthreads();
        float mx[4];
        #pragma unroll
        for (int q = 0; q < 4; q++)
            mx[q] = fmaxf(fmaxf(redA[0][q], redA[1][q]), fmaxf(redA[2][q], redA[3][q]));
        float ex[4];
        #pragma unroll
        for (int q = 0; q < 4; q++) {
            ex[q] = tmask ? 0.f : expf(sc[q] - mx[q]);
            v[q] = ex[q];
        }
        #pragma unroll
        for (int off = 16; off > 0; off >>= 1) {
            #pragma unroll
            for (int q = 0; q < 4; q++)
                v[q] += __shfl_xor_sync(0xffffffffu, v[q], off);
        }
        if (lane == 0) {
            #pragma unroll
            for (int q = 0; q < 4; q++) redB[warp][q] = v[q];
        }
        __syncthreads();
        float wgt[4];
        #pragma unroll
        for (int q = 0; q < 4; q++) {
            float sm = redB[0][q] + redB[1][q] + redB[2][q] + redB[3][q];
            wgt[q] = ex[q] / sm;
            w_sh[mi][t][q] = wgt[q];
            outW[((size_t)(b*Qx + q)*Mx + m)*Tx + t] = wgt[q];
        }
        // wc: 8 block reductions of w[q]*c[p]
        float vv[8];
        #pragma unroll
        for (int q = 0; q < 4; q++) { vv[q*2] = wgt[q]*c0; vv[q*2+1] = wgt[q]*c1; }
        #pragma unroll
        for (int off = 16; off > 0; off >>= 1) {
            #pragma unroll
            for (int k = 0; k < 8; k++)
                vv[k] += __shfl_xor_sync(0xffffffffu, vv[k], off);
        }
        if (lane == 0) {
            #pragma unroll
            for (int k = 0; k < 8; k++) redC[warp][k] = vv[k];
        }
        __syncthreads();
        if (t < 8) wc_sh[mi][t] = redC[0][t] + redC[1][t] + redC[2][t] + redC[3][t];
    }
    __syncthreads();

    // -------- phase 2: wh accumulate  (o = t, t+128) --------
    float acc0[TILE_M], acc1[TILE_M];
    #pragma unroll
    for (int mi = 0; mi < TILE_M; mi++) { acc0[mi] = 0.f; acc1[mi] = 0.f; }
    const float* ybase = gY + (size_t)b*Qx*Tx*Hx + t;
    for (int tt = 0; tt < xlen; tt++) {
        float4 wv[TILE_M];
        #pragma unroll
        for (int mi = 0; mi < TILE_M; mi++)
            wv[mi] = *(const float4*)&w_sh[mi][tt][0];
        #pragma unroll
        for (int q = 0; q < 4; q++) {
            const float* yp = ybase + ((size_t)(q*Tx + tt) << 8);
            float y0 = yp[0], y1 = yp[128];
            #pragma unroll
            for (int mi = 0; mi < TILE_M; mi++) {
                float w = (q == 0) ? wv[mi].x : (q == 1) ? wv[mi].y : (q == 2) ? wv[mi].z : wv[mi].w;
                acc0[mi] = fmaf(w, y0, acc0[mi]);
                acc1[mi] = fmaf(w, y1, acc1[mi]);
            }
        }
    }

    // -------- phase 3: u = wh + proj1_b + wc@proj2_w + proj2_b --------
    #pragma unroll
    for (int mi = 0; mi < TILE_M; mi++) {
        int m = m0 + mi;
        float u0 = 0.f, u1 = 0.f;
        if (m < mel_len) {
            u0 = acc0[mi] + p1b[t]       + p2b[t];
            u1 = acc1[mi] + p1b[t + 128] + p2b[t + 128];
            #pragma unroll
            for (int j = 0; j < 8; j++) {
                float wc = wc_sh[mi][j];
                u0 = fmaf(wc, p2w[j*Hx + t],       u0);
                u1 = fmaf(wc, p2w[j*Hx + t + 128], u1);
            }
        }
        u_sh[mi][t]       = u0;
        u_sh[mi][t + 128] = u1;
    }
    __syncthreads();

    // -------- phase 4: o = u @ projo_w + projo_b --------
    float acc2[4][TILE_M];
    #pragma unroll
    for (int r = 0; r < 4; r++)
        #pragma unroll
        for (int mi = 0; mi < TILE_M; mi++) acc2[r][mi] = 0.f;
    for (int h = 0; h < Hx; h++) {
        float uv[TILE_M];
        #pragma unroll
        for (int mi = 0; mi < TILE_M; mi++) uv[mi] = u_sh[mi][h];
        const float* prow = pow_ + (size_t)h*(2*Hx) + t;
        #pragma unroll
        for (int r = 0; r < 4; r++) {
            float pw = prow[r*128];
            #pragma unroll
            for (int mi = 0; mi < TILE_M; mi++)
                acc2[r][mi] = fmaf(uv[mi], pw, acc2[r][mi]);
        }
    }
    #pragma unroll
    for (int mi = 0; mi < TILE_M; mi++) {
        int m = m0 + mi;
        float* op = outO + (size_t)(b*Mx + m)*(2*Hx);
        #pragma unroll
        for (int r = 0; r < 4; r++) {
            int j = t + r*128;
            op[j] = acc2[r][mi] + pob[j];
        }
    }
}

// ------------------------- launch -------------------------
extern "C" void kernel_launch(void* const* d_in, const int* in_sizes, int n_in,
                              void* d_out, int out_size) {
    (void)in_sizes; (void)n_in; (void)out_size;
    const float* x        = (const float*)d_in[0];
    // d_in[1] = x_mask (bool) — derived from x_lengths instead
    const float* xdur     = (const float*)d_in[2];
    const int*   xlens    = (const int*)  d_in[3];
    const float* proj_w   = (const float*)d_in[4];
    const float* proj_b   = (const float*)d_in[5];
    const float* conv_w   = (const float*)d_in[6];
    const float* conv_b   = (const float*)d_in[7];
    const float* conv_g   = (const float*)d_in[8];
    const float* conv_bt  = (const float*)d_in[9];
    const float* q_w1     = (const float*)d_in[10];
    const float* q_b1     = (const float*)d_in[11];
    const float* q_g      = (const float*)d_in[12];
    const float* q_bt     = (const float*)d_in[13];
    const float* q_w2     = (const float*)d_in[14];
    const float* q_b2     = (const float*)d_in[15];
    const float* p_w1     = (const float*)d_in[16];
    const float* p_b1     = (const float*)d_in[17];
    const float* p_g      = (const float*)d_in[18];
    const float* p_bt     = (const float*)d_in[19];
    const float* p_w2     = (const float*)d_in[20];
    const float* p_b2     = (const float*)d_in[21];
    const float* proj1_w  = (const float*)d_in[22];
    const float* proj1_b  = (const float*)d_in[23];
    const float* proj2_w  = (const float*)d_in[24];
    const float* proj2_b  = (const float*)d_in[25];
    const float* projo_w  = (const float*)d_in[26];
    const float* projo_b  = (const float*)d_in[27];

    float* out     = (float*)d_out;
    float* outO    = out;                                    // B*M*2H
    float* outMask = out + (size_t)Bx*Mx*2*Hx;               // B*M*T
    float* outLens = outMask + (size_t)Bx*Mx*Tx;             // B
    float* outW    = outLens + Bx;                           // B*Q*M*T

    kDur <<<Bx, 32>>>(xdur, outLens);
    kH   <<<Bx*Tx/8, Hx>>>(x, proj_w, proj_b, xlens);
    kConv<<<Bx*Tx, Hx>>>(conv_w, conv_b, conv_g, conv_bt, xlens);
    kY   <<<Bx*Qx*(Tx/16), Hx>>>(x, proj1_w);
    kMain<<<Bx*NTILES, 128>>>(xlens,
        q_w1, q_b1, q_g, q_bt, q_w2, q_b2,
        p_w1, p_b1, p_g, p_bt, p_w2, p_b2,
        proj1_b, proj2_w, proj2_b, projo_w, projo_b,
        outO, outMask, outW);
}

// round 3
// speedup vs baseline: 1.0068x; 1.0068x over previous
#include <cuda_runtime.h>
#include <math.h>

#define Bx 32
#define Tx 128
#define Hx 256
#define Mx 1000
#define Qx 4
#define TILE_M 8
#define NTILES 125   // 1000 / 8

typedef unsigned long long ull;

__device__ __forceinline__ ull pack2(float a, float b) {
    ull r; asm("mov.b64 %0, {%1, %2};" : "=l"(r) : "f"(a), "f"(b)); return r;
}
__device__ __forceinline__ void unpack2(ull v, float& a, float& b) {
    asm("mov.b64 {%0, %1}, %2;" : "=f"(a), "=f"(b) : "l"(v));
}
__device__ __forceinline__ void ffma2(ull& d, ull a, ull b) {
    asm("fma.rn.f32x2 %0, %1, %2, %0;" : "+l"(d) : "l"(a), "l"(b));
}

// ------------------------- device scratch -------------------------
__device__ float gH [Bx*Tx*Hx];            // h = (x@proj_w + b) * valid   (4 MB)
__device__ float gHC[Bx*Tx*8];             // conv-block output
__device__ float gE [Bx*Tx];
__device__ float gS [Bx*Tx];
__device__ int   gML[Bx];
__device__ float gY [(size_t)Bx*Qx*Tx*Hx]; // Y[b,q,t,o]  (16 MB)

// ------------------------- kDur -------------------------
__global__ void kDur(const float* __restrict__ xdur, float* __restrict__ outLens) {
    int b = blockIdx.x;
    if (threadIdx.x == 0) {
        float run = 0.f;
        for (int t = 0; t < Tx; t++) {
            float d = xdur[b*Tx + t];
            gS[b*Tx + t] = run;
            run += d;
            gE[b*Tx + t] = run;
        }
        int ml = (int)rintf(run);
        if (ml > Mx) ml = Mx;
        gML[b] = ml;
        outLens[b] = (float)ml;
    }
}

// ------------------------- kH: h = (x@proj_w + b)*valid -------------------------
// block = (b, 16 t-rows), 256 threads: rgrp = tid>>6 owns 4 rows, o4 = (tid&63)*4
__global__ void __launch_bounds__(256) kH(const float* __restrict__ x,
                                          const float* __restrict__ pw,
                                          const float* __restrict__ pb,
                                          const int*   __restrict__ xlens) {
    __shared__ ull xd[16][Hx];   // duplicated f32x2, 32KB
    int b  = blockIdx.x >> 3;
    int t0 = (blockIdx.x & 7) * 16;
    int tid = threadIdx.x;

    #pragma unroll
    for (int i = 0; i < 16; i++) {
        float v = x[(size_t)(b*Tx + t0 + i)*Hx + tid];
        xd[i][tid] = pack2(v, v);
    }
    __syncthreads();

    int rgrp = tid >> 6;
    int o4   = (tid & 63) << 2;
    int r0   = rgrp * 4;

    ull acc[4][2];
    #pragma unroll
    for (int i = 0; i < 4; i++) { acc[i][0] = 0ull; acc[i][1] = 0ull; }

    for (int h = 0; h < Hx; h += 2) {
        ulonglong2 w0 = *reinterpret_cast<const ulonglong2*>(pw + (size_t)h*Hx + o4);
        ulonglong2 w1 = *reinterpret_cast<const ulonglong2*>(pw + (size_t)(h+1)*Hx + o4);
        #pragma unroll
        for (int i = 0; i < 4; i++) {
            ulonglong2 xv = *reinterpret_cast<const ulonglong2*>(&xd[r0 + i][h]);
            ffma2(acc[i][0], xv.x, w0.x);
            ffma2(acc[i][1], xv.x, w0.y);
            ffma2(acc[i][0], xv.y, w1.x);
            ffma2(acc[i][1], xv.y, w1.y);
        }
    }

    int xlen = xlens[b];
    float4 pbv = *reinterpret_cast<const float4*>(pb + o4);
    #pragma unroll
    for (int i = 0; i < 4; i++) {
        int row = t0 + r0 + i;
        float4 ov;
        unpack2(acc[i][0], ov.x, ov.y);
        unpack2(acc[i][1], ov.z, ov.w);
        ov.x += pbv.x; ov.y += pbv.y; ov.z += pbv.z; ov.w += pbv.w;
        if (row >= xlen) { ov.x = 0.f; ov.y = 0.f; ov.z = 0.f; ov.w = 0.f; }
        *reinterpret_cast<float4*>(&gH[(size_t)(b*Tx + row)*Hx + o4]) = ov;
    }
}

// ------------------------- kConv: conv1d(k=3) + LN(8) + silu, *valid -------------------------
__global__ void __launch_bounds__(Hx) kConv(const float* __restrict__ cw,
                                            const float* __restrict__ cb,
                                            const float* __restrict__ cg,
                                            const float* __restrict__ cbeta,
                                            const int*   __restrict__ xlens) {
    int bt = blockIdx.x;
    int b = bt >> 7, t = bt & 127;
    int cin = threadIdx.x;

    float hm = (t > 0)   ? gH[(size_t)(bt-1)*Hx + cin] : 0.f;
    float h0 =             gH[(size_t) bt   *Hx + cin];
    float hp = (t < 127) ? gH[(size_t)(bt+1)*Hx + cin] : 0.f;

    float loc[8];
    #pragma unroll
    for (int c = 0; c < 8; c++) {
        const float* w = cw + c*(Hx*3) + cin*3;
        loc[c] = fmaf(w[0], hm, fmaf(w[1], h0, w[2]*hp));
    }
    #pragma unroll
    for (int off = 16; off > 0; off >>= 1) {
        #pragma unroll
        for (int c = 0; c < 8; c++)
            loc[c] += __shfl_xor_sync(0xffffffffu, loc[c], off);
    }
    __shared__ float red[8][8];
    __shared__ float tmp8[8];
    int warp = cin >> 5, lane = cin & 31;
    if (lane == 0) {
        #pragma unroll
        for (int c = 0; c < 8; c++) red[warp][c] = loc[c];
    }
    __syncthreads();
    if (cin < 8) {
        float v = cb[cin];
        #pragma unroll
        for (int w = 0; w < 8; w++) v += red[w][cin];
        tmp8[cin] = v;
    }
    __syncthreads();
    if (cin < 8) {
        float mu = 0.f;
        #pragma unroll
        for (int j = 0; j < 8; j++) mu += tmp8[j];
        mu *= 0.125f;
        float var = 0.f;
        #pragma unroll
        for (int j = 0; j < 8; j++) { float d = tmp8[j]-mu; var = fmaf(d, d, var); }
        var *= 0.125f;
        float zn = (tmp8[cin]-mu) * rsqrtf(var + 1e-5f) * cg[cin] + cbeta[cin];
        float sil = zn / (1.f + expf(-zn));
        gHC[bt*8 + cin] = (t < xlens[b]) ? sil : 0.f;
    }
}

// ------------------------- kY: Y[b,q,t,o] = x[b,t,:] @ proj1_w[q*H+:, o] -------------------------
// block = (b, 8 t-rows), 256 threads: q = tid>>6, o4 = (tid&63)*4
__global__ void __launch_bounds__(256) kY(const float* __restrict__ x,
                                          const float* __restrict__ p1w) {
    __shared__ ull xd[8][Hx];   // duplicated f32x2, 16KB
    int b  = blockIdx.x >> 4;
    int t0 = (blockIdx.x & 15) * 8;
    int tid = threadIdx.x;

    #pragma unroll
    for (int i = 0; i < 8; i++) {
        float v = x[(size_t)(b*Tx + t0 + i)*Hx + tid];
        xd[i][tid] = pack2(v, v);
    }
    __syncthreads();

    int q  = tid >> 6;
    int o4 = (tid & 63) << 2;

    ull acc[8][2];
    #pragma unroll
    for (int i = 0; i < 8; i++) { acc[i][0] = 0ull; acc[i][1] = 0ull; }

    const float* wb = p1w + (size_t)q*Hx*Hx + o4;
    for (int h = 0; h < Hx; h += 2) {
        ulonglong2 w0 = *reinterpret_cast<const ulonglong2*>(wb + (size_t)h*Hx);
        ulonglong2 w1 = *reinterpret_cast<const ulonglong2*>(wb + (size_t)(h+1)*Hx);
        #pragma unroll
        for (int i = 0; i < 8; i++) {
            ulonglong2 xv = *reinterpret_cast<const ulonglong2*>(&xd[i][h]);
            ffma2(acc[i][0], xv.x, w0.x);
            ffma2(acc[i][1], xv.x, w0.y);
            ffma2(acc[i][0], xv.y, w1.x);
            ffma2(acc[i][1], xv.y, w1.y);
        }
    }

    #pragma unroll
    for (int i = 0; i < 8; i++) {
        float4 ov;
        unpack2(acc[i][0], ov.x, ov.y);
        unpack2(acc[i][1], ov.z, ov.w);
        *reinterpret_cast<float4*>(&gY[(size_t)((b*Qx + q)*Tx + t0 + i)*Hx + o4]) = ov;
    }
}

// ------------------------- kMain -------------------------
// shared pool aliases: w_shd (phase1/2) then u_shd (phase3/4)
#define W_SHD(mi,tt,qq) pool[(((mi)<<7) + (tt))*4 + (qq)]
#define U_SHD(mi,h)     pool[((mi)<<8) + (h)]

__global__ void __launch_bounds__(128) kMain(
    const int*   __restrict__ xlens,
    const float* __restrict__ qw1, const float* __restrict__ qb1,
    const float* __restrict__ qg,  const float* __restrict__ qbeta,
    const float* __restrict__ qw2, const float* __restrict__ qb2,
    const float* __restrict__ pw1, const float* __restrict__ pb1,
    const float* __restrict__ pg,  const float* __restrict__ pbeta,
    const float* __restrict__ pw2, const float* __restrict__ pb2,
    const float* __restrict__ p1b, const float* __restrict__ p2w,
    const float* __restrict__ p2b, const float* __restrict__ pow_,
    const float* __restrict__ pob,
    float* __restrict__ outO, float* __restrict__ outMask,
    float* __restrict__ outW)
{
    __shared__ ull  pool[TILE_M*Tx*4];   // 32KB: w_shd then u_shd
    __shared__ float wc_sh[TILE_M][8];
    __shared__ float redA[4][4];
    __shared__ float redB[4][4];
    __shared__ float redC[4][8];

    int b    = blockIdx.x / NTILES;
    int tile = blockIdx.x % NTILES;
    int m0   = tile * TILE_M;
    int t    = threadIdx.x;
    int warp = t >> 5, lane = t & 31;
    int mel_len = gML[b];
    int xlen    = xlens[b];

    // -------- fully padded tile fast path --------
    if (m0 >= mel_len) {
        int j4 = t << 2;
        float4 pb4 = *reinterpret_cast<const float4*>(pob + j4);
        #pragma unroll
        for (int mi = 0; mi < TILE_M; mi++) {
            int m = m0 + mi;
            outMask[(size_t)(b*Mx + m)*Tx + t] = 1.f;
            #pragma unroll
            for (int q = 0; q < 4; q++)
                outW[((size_t)(b*Qx + q)*Mx + m)*Tx + t] = 0.f;
            *reinterpret_cast<float4*>(outO + (size_t)(b*Mx + m)*(2*Hx) + j4) = pb4;
        }
        return;
    }

    bool tmask = (t >= xlen);
    float fh[8];
    #pragma unroll
    for (int c = 0; c < 8; c++) fh[c] = gHC[(b*Tx + t)*8 + c];
    float se = gE[b*Tx + t], ss = gS[b*Tx + t];

    // m-independent parts of the two tiny MLPs
    float zqb[4];
    #pragma unroll
    for (int q = 0; q < 4; q++) zqb[q] = qb1[q];
    #pragma unroll
    for (int i = 0; i < 8; i++) {
        #pragma unroll
        for (int q = 0; q < 4; q++) zqb[q] = fmaf(fh[i], qw1[i*4 + q], zqb[q]);
    }
    float zpb0 = pb1[0], zpb1 = pb1[1];
    #pragma unroll
    for (int i = 0; i < 8; i++) {
        zpb0 = fmaf(fh[i], pw1[i*2 + 0], zpb0);
        zpb1 = fmaf(fh[i], pw1[i*2 + 1], zpb1);
    }

    // -------- phase 1: per-m scores, softmax, wc --------
    for (int mi = 0; mi < TILE_M; mi++) {
        int m = m0 + mi;
        bool pad = (m >= mel_len);
        outMask[(size_t)(b*Mx + m)*Tx + t] = pad ? 1.f : 0.f;
        if (pad) {
            #pragma unroll
            for (int q = 0; q < 4; q++) {
                W_SHD(mi, t, q) = 0ull;
                outW[((size_t)(b*Qx + q)*Mx + m)*Tx + t] = 0.f;
            }
            if (t < 8) wc_sh[mi][t] = 0.f;
            continue;
        }
        float tf = (float)(m + 1);
        float f8 = tmask ? 0.f : (tf - ss);
        float f9 = tmask ? 0.f : (se - tf);

        // q-MLP
        float z[4];
        #pragma unroll
        for (int q = 0; q < 4; q++)
            z[q] = fmaf(f9, qw1[36 + q], fmaf(f8, qw1[32 + q], zqb[q]));
        float mu = 0.25f * (z[0] + z[1] + z[2] + z[3]);
        float var = 0.f;
        #pragma unroll
        for (int q = 0; q < 4; q++) { float d = z[q]-mu; var = fmaf(d, d, var); }
        var *= 0.25f;
        float rinv = rsqrtf(var + 1e-5f);
        float a[4];
        #pragma unroll
        for (int q = 0; q < 4; q++) {
            float zn = (z[q]-mu) * rinv * qg[q] + qbeta[q];
            a[q] = zn / (1.f + expf(-zn));
        }
        float sc[4];
        #pragma unroll
        for (int q = 0; q < 4; q++) {
            float s = qb2[q];
            #pragma unroll
            for (int j = 0; j < 4; j++) s = fmaf(a[j], qw2[j*4 + q], s);
            sc[q] = tmask ? -1e30f : s;
        }

        // p-MLP
        float zp0 = fmaf(f9, pw1[18], fmaf(f8, pw1[16], zpb0));
        float zp1 = fmaf(f9, pw1[19], fmaf(f8, pw1[17], zpb1));
        float mup  = 0.5f * (zp0 + zp1);
        float d0 = zp0 - mup, d1 = zp1 - mup;
        float varp = 0.5f * (d0*d0 + d1*d1);
        float rp = rsqrtf(varp + 1e-5f);
        float a0 = d0 * rp * pg[0] + pbeta[0];
        float a1 = d1 * rp * pg[1] + pbeta[1];
        a0 = a0 / (1.f + expf(-a0));
        a1 = a1 / (1.f + expf(-a1));
        float c0 = fmaf(a1, pw2[2], fmaf(a0, pw2[0], pb2[0]));
        float c1 = fmaf(a1, pw2[3], fmaf(a0, pw2[1], pb2[1]));

        // block softmax over t, 4 q's at once
        float v[4];
        #pragma unroll
        for (int q = 0; q < 4; q++) v[q] = sc[q];
        #pragma unroll
        for (int off = 16; off > 0; off >>= 1) {
            #pragma unroll
            for (int q = 0; q < 4; q++)
                v[q] = fmaxf(v[q], __shfl_xor_sync(0xffffffffu, v[q], off));
        }
        if (lane == 0) {
            #pragma unroll
            for (int q = 0; q < 4; q++) redA[warp][q] = v[q];
        }
        __syncthreads();
        float mx[4];
        #pragma unroll
        for (int q = 0; q < 4; q++)
            mx[q] = fmaxf(fmaxf(redA[0][q], redA[1][q]), fmaxf(redA[2][q], redA[3][q]));
        float ex[4];
        #pragma unroll
        for (int q = 0; q < 4; q++) {
            ex[q] = tmask ? 0.f : expf(sc[q] - mx[q]);
            v[q] = ex[q];
        }
        #pragma unroll
        for (int off = 16; off > 0; off >>= 1) {
            #pragma unroll
            for (int q = 0; q < 4; q++)
                v[q] += __shfl_xor_sync(0xffffffffu, v[q], off);
        }
        if (lane == 0) {
            #pragma unroll
            for (int q = 0; q < 4; q++) redB[warp][q] = v[q];
        }
        __syncthreads();
        float wgt[4];
        #pragma unroll
        for (int q = 0; q < 4; q++) {
            float sm = redB[0][q] + redB[1][q] + redB[2][q] + redB[3][q];
            wgt[q] = ex[q] / sm;
            W_SHD(mi, t, q) = pack2(wgt[q], wgt[q]);
            outW[((size_t)(b*Qx + q)*Mx + m)*Tx + t] = wgt[q];
        }
        // wc: 8 block reductions of w[q]*c[p]
        float vv[8];
        #pragma unroll
        for (int q = 0; q < 4; q++) { vv[q*2] = wgt[q]*c0; vv[q*2+1] = wgt[q]*c1; }
        #pragma unroll
        for (int off = 16; off > 0; off >>= 1) {
            #pragma unroll
            for (int k = 0; k < 8; k++)
                vv[k] += __shfl_xor_sync(0xffffffffu, vv[k], off);
        }
        if (lane == 0) {
            #pragma unroll
            for (int k = 0; k < 8; k++) redC[warp][k] = vv[k];
        }
        __syncthreads();
        if (t < 8) wc_sh[mi][t] = redC[0][t] + redC[1][t] + redC[2][t] + redC[3][t];
    }
    __syncthreads();

    // -------- phase 2: wh accumulate --------
    // grp = t>>6 owns m = grp*4 + mi (4 m's), o4 = (t&63)*4 (4 outputs, packed as 2 f32x2)
    int grp = t >> 6;
    int gm  = grp * 4;
    int o4  = (t & 63) << 2;

    ull accp[4][2];
    #pragma unroll
    for (int mi = 0; mi < 4; mi++) { accp[mi][0] = 0ull; accp[mi][1] = 0ull; }

    const float* yb = gY + (size_t)b*Qx*Tx*Hx + o4;
    for (int tt = 0; tt < xlen; tt++) {
        ull wp[4][4];
        #pragma unroll
        for (int mi = 0; mi < 4; mi++) {
            const ulonglong2* p = reinterpret_cast<const ulonglong2*>(&W_SHD(gm + mi, tt, 0));
            ulonglong2 w01 = p[0], w23 = p[1];
            wp[mi][0] = w01.x; wp[mi][1] = w01.y; wp[mi][2] = w23.x; wp[mi][3] = w23.y;
        }
        #pragma unroll
        for (int q = 0; q < 4; q++) {
            ulonglong2 y = *reinterpret_cast<const ulonglong2*>(yb + ((size_t)(q*Tx + tt) << 8));
            #pragma unroll
            for (int mi = 0; mi < 4; mi++) {
                ffma2(accp[mi][0], wp[mi][q], y.x);
                ffma2(accp[mi][1], wp[mi][q], y.y);
            }
        }
    }
    __syncthreads();   // all reads of w_shd done before pool is reused as u_shd

    // -------- phase 3: u = wh + proj1_b + wc@proj2_w + proj2_b --------
    {
        float4 b1 = *reinterpret_cast<const float4*>(p1b + o4);
        float4 b2 = *reinterpret_cast<const float4*>(p2b + o4);
        float4 pp[8];
        #pragma unroll
        for (int j = 0; j < 8; j++)
            pp[j] = *reinterpret_cast<const float4*>(p2w + j*Hx + o4);
        #pragma unroll
        for (int mi = 0; mi < 4; mi++) {
            int m = m0 + gm + mi;
            float u[4];
            if (m < mel_len) {
                unpack2(accp[mi][0], u[0], u[1]);
                unpack2(accp[mi][1], u[2], u[3]);
                u[0] += b1.x + b2.x; u[1] += b1.y + b2.y;
                u[2] += b1.z + b2.z; u[3] += b1.w + b2.w;
                #pragma unroll
                for (int j = 0; j < 8; j++) {
                    float wc = wc_sh[gm + mi][j];
                    u[0] = fmaf(wc, pp[j].x, u[0]);
                    u[1] = fmaf(wc, pp[j].y, u[1]);
                    u[2] = fmaf(wc, pp[j].z, u[2]);
                    u[3] = fmaf(wc, pp[j].w, u[3]);
                }
            } else {
                u[0] = u[1] = u[2] = u[3] = 0.f;
            }
            #pragma unroll
            for (int k = 0; k < 4; k++)
                U_SHD(gm + mi, o4 + k) = pack2(u[k], u[k]);
        }
    }
    __syncthreads();

    // -------- phase 4: o = u @ projo_w + projo_b --------
    int j4 = t << 2;   // 0..508
    ull acco[TILE_M][2];
    #pragma unroll
    for (int mi = 0; mi < TILE_M; mi++) { acco[mi][0] = 0ull; acco[mi][1] = 0ull; }

    for (int h = 0; h < Hx; h += 2) {
        ulonglong2 pw0 = *reinterpret_cast<const ulonglong2*>(pow_ + (size_t)h*(2*Hx) + j4);
        ulonglong2 pw1 = *reinterpret_cast<const ulonglong2*>(pow_ + (size_t)(h+1)*(2*Hx) + j4);
        #pragma unroll
        for (int mi = 0; mi < TILE_M; mi++) {
            ulonglong2 ud = *reinterpret_cast<const ulonglong2*>(&U_SHD(mi, h));
            ffma2(acco[mi][0], ud.x, pw0.x);
            ffma2(acco[mi][1], ud.x, pw0.y);
            ffma2(acco[mi][0], ud.y, pw1.x);
            ffma2(acco[mi][1], ud.y, pw1.y);
        }
    }
    float4 pb4 = *reinterpret_cast<const float4*>(pob + j4);
    #pragma unroll
    for (int mi = 0; mi < TILE_M; mi++) {
        int m = m0 + mi;
        float4 ov;
        unpack2(acco[mi][0], ov.x, ov.y);
        unpack2(acco[mi][1], ov.z, ov.w);
        ov.x += pb4.x; ov.y += pb4.y; ov.z += pb4.z; ov.w += pb4.w;
        *reinterpret_cast<float4*>(outO + (size_t)(b*Mx + m)*(2*Hx) + j4) = ov;
    }
}

// ------------------------- launch -------------------------
extern "C" void kernel_launch(void* const* d_in, const int* in_sizes, int n_in,
                              void* d_out, int out_size) {
    (void)in_sizes; (void)n_in; (void)out_size;
    const float* x        = (const float*)d_in[0];
    const float* xdur     = (const float*)d_in[2];
    const int*   xlens    = (const int*)  d_in[3];
    const float* proj_w   = (const float*)d_in[4];
    const float* proj_b   = (const float*)d_in[5];
    const float* conv_w   = (const float*)d_in[6];
    const float* conv_b   = (const float*)d_in[7];
    const float* conv_g   = (const float*)d_in[8];
    const float* conv_bt  = (const float*)d_in[9];
    const float* q_w1     = (const float*)d_in[10];
    const float* q_b1     = (const float*)d_in[11];
    const float* q_g      = (const float*)d_in[12];
    const float* q_bt     = (const float*)d_in[13];
    const float* q_w2     = (const float*)d_in[14];
    const float* q_b2     = (const float*)d_in[15];
    const float* p_w1     = (const float*)d_in[16];
    const float* p_b1     = (const float*)d_in[17];
    const float* p_g      = (const float*)d_in[18];
    const float* p_bt     = (const float*)d_in[19];
    const float* p_w2     = (const float*)d_in[20];
    const float* p_b2     = (const float*)d_in[21];
    const float* proj1_w  = (const float*)d_in[22];
    const float* proj1_b  = (const float*)d_in[23];
    const float* proj2_w  = (const float*)d_in[24];
    const float* proj2_b  = (const float*)d_in[25];
    const float* projo_w  = (const float*)d_in[26];
    const float* projo_b  = (const float*)d_in[27];

    float* out     = (float*)d_out;
    float* outO    = out;                                    // B*M*2H
    float* outMask = out + (size_t)Bx*Mx*2*Hx;               // B*M*T
    float* outLens = outMask + (size_t)Bx*Mx*Tx;             // B
    float* outW    = outLens + Bx;                           // B*Q*M*T

    kDur <<<Bx, 32>>>(xdur, outLens);
    kH   <<<Bx*(Tx/16), 256>>>(x, proj_w, proj_b, xlens);
    kConv<<<Bx*Tx, Hx>>>(conv_w, conv_b, conv_g, conv_bt, xlens);
    kY   <<<Bx*(Tx/8), 256>>>(x, proj1_w);
    kMain<<<Bx*NTILES, 128>>>(xlens,
        q_w1, q_b1, q_g, q_bt, q_w2, q_b2,
        p_w1, p_b1, p_g, p_bt, p_w2, p_b2,
        proj1_b, proj2_w, proj2_b, projo_w, projo_b,
        outO, outMask, outW);
}

// round 4
// speedup vs baseline: 1.0911x; 1.0838x over previous
#include <cuda_runtime.h>
#include <math.h>

#define Bx 32
#define Tx 128
#define Hx 256
#define Mx 1000
#define Qx 4
#define TILE_M 8
#define NTILES 125   // 1000 / 8

// ------------------------- device scratch -------------------------
__device__ float gH [Bx*Tx*Hx];            // h = (x@proj_w + b) * valid
__device__ float gHC[Bx*Tx*8];             // conv-block output
__device__ float gE [Bx*Tx];
__device__ float gS [Bx*Tx];
__device__ int   gML[Bx];
__device__ float gY [(size_t)Bx*Qx*Tx*Hx]; // Y[b,q,t,o]  (16 MB)

// ------------------------- kDur -------------------------
__global__ void kDur(const float* __restrict__ xdur, float* __restrict__ outLens) {
    int b = blockIdx.x;
    if (threadIdx.x == 0) {
        float run = 0.f;
        for (int t = 0; t < Tx; t++) {
            float d = xdur[b*Tx + t];
            gS[b*Tx + t] = run;
            run += d;
            gE[b*Tx + t] = run;
        }
        int ml = (int)rintf(run);
        if (ml > Mx) ml = Mx;
        gML[b] = ml;
        outLens[b] = (float)ml;
    }
}

// ------------------------- kHY: fused x@proj_w (seg 0) and x@proj1_w_q (segs 1-4) -----
// grid (Bx, 4 row-tiles, 5 segs); block 256.
// Block computes C[32 t-rows][256 cols] = x_tile(32x256) @ W_seg(256x256).
// Thread: rg = tid>>6 owns rows rg*8..rg*8+7; og = tid&63 owns cols og*4..og*4+3.
__global__ void __launch_bounds__(256) kHY(const float* __restrict__ x,
                                           const float* __restrict__ proj_w,
                                           const float* __restrict__ proj_b,
                                           const float* __restrict__ p1w,
                                           const int*   __restrict__ xlens) {
    __shared__ float xs[32][Hx];   // 32KB
    int b   = blockIdx.x;
    int t0  = blockIdx.y * 32;
    int seg = blockIdx.z;
    int tid = threadIdx.x;

    #pragma unroll
    for (int i = 0; i < 32; i += 8)
        xs[i + (tid >> 5)][tid & 31 ? 0 : 0], xs[i + (tid >> 8)][0] = xs[i + (tid >> 8)][0]; // no-op guard
    // cooperative load: each thread loads 32 elements (one column tid across 32 rows)
    #pragma unroll
    for (int i = 0; i < 32; i++)
        xs[i][tid] = x[(size_t)(b*Tx + t0 + i)*Hx + tid];
    __syncthreads();

    const float* W = (seg == 0) ? proj_w : (p1w + (size_t)(seg-1)*Hx*Hx);
    int rg = tid >> 6;            // 0..3
    int og = tid & 63;            // 0..63
    int o4 = og << 2;
    int r0 = rg << 3;

    float acc[8][4];
    #pragma unroll
    for (int i = 0; i < 8; i++)
        #pragma unroll
        for (int j = 0; j < 4; j++) acc[i][j] = 0.f;

    #pragma unroll 4
    for (int h = 0; h < Hx; h++) {
        float4 w = *reinterpret_cast<const float4*>(W + (size_t)h*Hx + o4);
        #pragma unroll
        for (int i = 0; i < 8; i++) {
            float xv = xs[r0 + i][h];
            acc[i][0] = fmaf(xv, w.x, acc[i][0]);
            acc[i][1] = fmaf(xv, w.y, acc[i][1]);
            acc[i][2] = fmaf(xv, w.z, acc[i][2]);
            acc[i][3] = fmaf(xv, w.w, acc[i][3]);
        }
    }

    if (seg == 0) {
        int xlen = xlens[b];
        float4 pbv = *reinterpret_cast<const float4*>(proj_b + o4);
        #pragma unroll
        for (int i = 0; i < 8; i++) {
            int row = t0 + r0 + i;
            float4 ov;
            ov.x = acc[i][0] + pbv.x; ov.y = acc[i][1] + pbv.y;
            ov.z = acc[i][2] + pbv.z; ov.w = acc[i][3] + pbv.w;
            if (row >= xlen) { ov.x = 0.f; ov.y = 0.f; ov.z = 0.f; ov.w = 0.f; }
            *reinterpret_cast<float4*>(&gH[(size_t)(b*Tx + row)*Hx + o4]) = ov;
        }
    } else {
        int q = seg - 1;
        #pragma unroll
        for (int i = 0; i < 8; i++) {
            int row = t0 + r0 + i;
            float4 ov = make_float4(acc[i][0], acc[i][1], acc[i][2], acc[i][3]);
            *reinterpret_cast<float4*>(&gY[(size_t)((b*Qx + q)*Tx + row)*Hx + o4]) = ov;
        }
    }
}

// ------------------------- kConv: conv1d(k=3) + LN(8) + silu, *valid -------------------------
__global__ void __launch_bounds__(Hx) kConv(const float* __restrict__ cw,
                                            const float* __restrict__ cb,
                                            const float* __restrict__ cg,
                                            const float* __restrict__ cbeta,
                                            const int*   __restrict__ xlens) {
    int bt = blockIdx.x;
    int b = bt >> 7, t = bt & 127;
    int cin = threadIdx.x;

    float hm = (t > 0)   ? gH[(size_t)(bt-1)*Hx + cin] : 0.f;
    float h0 =             gH[(size_t) bt   *Hx + cin];
    float hp = (t < 127) ? gH[(size_t)(bt+1)*Hx + cin] : 0.f;

    float loc[8];
    #pragma unroll
    for (int c = 0; c < 8; c++) {
        const float* w = cw + c*(Hx*3) + cin*3;
        loc[c] = fmaf(w[0], hm, fmaf(w[1], h0, w[2]*hp));
    }
    #pragma unroll
    for (int off = 16; off > 0; off >>= 1) {
        #pragma unroll
        for (int c = 0; c < 8; c++)
            loc[c] += __shfl_xor_sync(0xffffffffu, loc[c], off);
    }
    __shared__ float red[8][8];
    __shared__ float tmp8[8];
    int warp = cin >> 5, lane = cin & 31;
    if (lane == 0) {
        #pragma unroll
        for (int c = 0; c < 8; c++) red[warp][c] = loc[c];
    }
    __syncthreads();
    if (cin < 8) {
        float v = cb[cin];
        #pragma unroll
        for (int w = 0; w < 8; w++) v += red[w][cin];
        tmp8[cin] = v;
    }
    __syncthreads();
    if (cin < 8) {
        float mu = 0.f;
        #pragma unroll
        for (int j = 0; j < 8; j++) mu += tmp8[j];
        mu *= 0.125f;
        float var = 0.f;
        #pragma unroll
        for (int j = 0; j < 8; j++) { float d = tmp8[j]-mu; var = fmaf(d, d, var); }
        var *= 0.125f;
        float zn = (tmp8[cin]-mu) * rsqrtf(var + 1e-5f) * cg[cin] + cbeta[cin];
        float sil = zn / (1.f + expf(-zn));
        gHC[bt*8 + cin] = (t < xlens[b]) ? sil : 0.f;
    }
}

// ------------------------- kMain -------------------------
__global__ void __launch_bounds__(128) kMain(
    const int*   __restrict__ xlens,
    const float* __restrict__ qw1, const float* __restrict__ qb1,
    const float* __restrict__ qg,  const float* __restrict__ qbeta,
    const float* __restrict__ qw2, const float* __restrict__ qb2,
    const float* __restrict__ pw1, const float* __restrict__ pb1,
    const float* __restrict__ pg,  const float* __restrict__ pbeta,
    const float* __restrict__ pw2, const float* __restrict__ pb2,
    const float* __restrict__ p1b, const float* __restrict__ p2w,
    const float* __restrict__ p2b, const float* __restrict__ pow_,
    const float* __restrict__ pob,
    float* __restrict__ outO, float* __restrict__ outMask,
    float* __restrict__ outW)
{
    __shared__ float w_sh[TILE_M][Tx][4];   // 16KB
    __shared__ float u_sh[TILE_M][Hx];      // 8KB
    __shared__ float wc_sh[TILE_M][8];
    __shared__ float redA[4][4];
    __shared__ float redB[4][4];
    __shared__ float redC[4][8];

    int b    = blockIdx.x / NTILES;
    int tile = blockIdx.x % NTILES;
    int m0   = tile * TILE_M;
    int t    = threadIdx.x;
    int warp = t >> 5, lane = t & 31;
    int mel_len = gML[b];
    int xlen    = xlens[b];

    // -------- fully padded tile fast path --------
    if (m0 >= mel_len) {
        int j4 = t << 2;
        float4 pb4 = *reinterpret_cast<const float4*>(pob + j4);
        #pragma unroll
        for (int mi = 0; mi < TILE_M; mi++) {
            int m = m0 + mi;
            outMask[(size_t)(b*Mx + m)*Tx + t] = 1.f;
            #pragma unroll
            for (int q = 0; q < 4; q++)
                outW[((size_t)(b*Qx + q)*Mx + m)*Tx + t] = 0.f;
            *reinterpret_cast<float4*>(outO + (size_t)(b*Mx + m)*(2*Hx) + j4) = pb4;
        }
        return;
    }

    bool tmask = (t >= xlen);
    float fh[8];
    #pragma unroll
    for (int c = 0; c < 8; c++) fh[c] = gHC[(b*Tx + t)*8 + c];
    float se = gE[b*Tx + t], ss = gS[b*Tx + t];

    // m-independent parts of the two tiny MLPs
    float zqb[4];
    #pragma unroll
    for (int q = 0; q < 4; q++) zqb[q] = qb1[q];
    #pragma unroll
    for (int i = 0; i < 8; i++) {
        #pragma unroll
        for (int q = 0; q < 4; q++) zqb[q] = fmaf(fh[i], qw1[i*4 + q], zqb[q]);
    }
    float zpb0 = pb1[0], zpb1 = pb1[1];
    #pragma unroll
    for (int i = 0; i < 8; i++) {
        zpb0 = fmaf(fh[i], pw1[i*2 + 0], zpb0);
        zpb1 = fmaf(fh[i], pw1[i*2 + 1], zpb1);
    }

    // -------- phase 1: per-m scores, softmax, wc --------
    for (int mi = 0; mi < TILE_M; mi++) {
        int m = m0 + mi;
        bool pad = (m >= mel_len);
        outMask[(size_t)(b*Mx + m)*Tx + t] = pad ? 1.f : 0.f;
        if (pad) {
            #pragma unroll
            for (int q = 0; q < 4; q++) {
                w_sh[mi][t][q] = 0.f;
                outW[((size_t)(b*Qx + q)*Mx + m)*Tx + t] = 0.f;
            }
            if (t < 8) wc_sh[mi][t] = 0.f;
            continue;
        }
        float tf = (float)(m + 1);
        float f8 = tmask ? 0.f : (tf - ss);
        float f9 = tmask ? 0.f : (se - tf);

        // q-MLP
        float z[4];
        #pragma unroll
        for (int q = 0; q < 4; q++)
            z[q] = fmaf(f9, qw1[36 + q], fmaf(f8, qw1[32 + q], zqb[q]));
        float mu = 0.25f * (z[0] + z[1] + z[2] + z[3]);
        float var = 0.f;
        #pragma unroll
        for (int q = 0; q < 4; q++) { float d = z[q]-mu; var = fmaf(d, d, var); }
        var *= 0.25f;
        float rinv = rsqrtf(var + 1e-5f);
        float a[4];
        #pragma unroll
        for (int q = 0; q < 4; q++) {
            float zn = (z[q]-mu) * rinv * qg[q] + qbeta[q];
            a[q] = zn / (1.f + expf(-zn));
        }
        float sc[4];
        #pragma unroll
        for (int q = 0; q < 4; q++) {
            float s = qb2[q];
            #pragma unroll
            for (int j = 0; j < 4; j++) s = fmaf(a[j], qw2[j*4 + q], s);
            sc[q] = tmask ? -1e30f : s;
        }

        // p-MLP
        float zp0 = fmaf(f9, pw1[18], fmaf(f8, pw1[16], zpb0));
        float zp1 = fmaf(f9, pw1[19], fmaf(f8, pw1[17], zpb1));
        float mup  = 0.5f * (zp0 + zp1);
        float d0 = zp0 - mup, d1 = zp1 - mup;
        float varp = 0.5f * (d0*d0 + d1*d1);
        float rp = rsqrtf(varp + 1e-5f);
        float a0 = d0 * rp * pg[0] + pbeta[0];
        float a1 = d1 * rp * pg[1] + pbeta[1];
        a0 = a0 / (1.f + expf(-a0));
        a1 = a1 / (1.f + expf(-a1));
        float c0 = fmaf(a1, pw2[2], fmaf(a0, pw2[0], pb2[0]));
        float c1 = fmaf(a1, pw2[3], fmaf(a0, pw2[1], pb2[1]));

        // block softmax over t, 4 q's at once
        float v[4];
        #pragma unroll
        for (int q = 0; q < 4; q++) v[q] = sc[q];
        #pragma unroll
        for (int off = 16; off > 0; off >>= 1) {
            #pragma unroll
            for (int q = 0; q < 4; q++)
                v[q] = fmaxf(v[q], __shfl_xor_sync(0xffffffffu, v[q], off));
        }
        if (lane == 0) {
            #pragma unroll
            for (int q = 0; q < 4; q++) redA[warp][q] = v[q];
        }
        __syncthreads();
        float mx[4];
        #pragma unroll
        for (int q = 0; q < 4; q++)
            mx[q] = fmaxf(fmaxf(redA[0][q], redA[1][q]), fmaxf(redA[2][q], redA[3][q]));
        float ex[4];
        #pragma unroll
        for (int q = 0; q < 4; q++) {
            ex[q] = tmask ? 0.f : expf(sc[q] - mx[q]);
            v[q] = ex[q];
        }
        #pragma unroll
        for (int off = 16; off > 0; off >>= 1) {
            #pragma unroll
            for (int q = 0; q < 4; q++)
                v[q] += __shfl_xor_sync(0xffffffffu, v[q], off);
        }
        if (lane == 0) {
            #pragma unroll
            for (int q = 0; q < 4; q++) redB[warp][q] = v[q];
        }
        __syncthreads();
        float wgt[4];
        #pragma unroll
        for (int q = 0; q < 4; q++) {
            float sm = redB[0][q] + redB[1][q] + redB[2][q] + redB[3][q];
            wgt[q] = ex[q] / sm;
            w_sh[mi][t][q] = wgt[q];
            outW[((size_t)(b*Qx + q)*Mx + m)*Tx + t] = wgt[q];
        }
        // wc: 8 block reductions of w[q]*c[p]
        float vv[8];
        #pragma unroll
        for (int q = 0; q < 4; q++) { vv[q*2] = wgt[q]*c0; vv[q*2+1] = wgt[q]*c1; }
        #pragma unroll
        for (int off = 16; off > 0; off >>= 1) {
            #pragma unroll
            for (int k = 0; k < 8; k++)
                vv[k] += __shfl_xor_sync(0xffffffffu, vv[k], off);
        }
        if (lane == 0) {
            #pragma unroll
            for (int k = 0; k < 8; k++) redC[warp][k] = vv[k];
        }
        __syncthreads();
        if (t < 8) wc_sh[mi][t] = redC[0][t] + redC[1][t] + redC[2][t] + redC[3][t];
    }
    __syncthreads();

    // -------- phase 2: wh accumulate (thread owns 8 m x 2 adjacent o) --------
    int o2 = t << 1;   // 0..254
    float acc0[TILE_M], acc1[TILE_M];
    #pragma unroll
    for (int mi = 0; mi < TILE_M; mi++) { acc0[mi] = 0.f; acc1[mi] = 0.f; }

    const float* yb = gY + (size_t)b*Qx*Tx*Hx + o2;
    #pragma unroll 2
    for (int tt = 0; tt < xlen; tt++) {
        float4 wv[TILE_M];
        #pragma unroll
        for (int mi = 0; mi < TILE_M; mi++)
            wv[mi] = *reinterpret_cast<const float4*>(&w_sh[mi][tt][0]);
        float2 y0 = *reinterpret_cast<const float2*>(yb + ((size_t)(0*Tx + tt) << 8));
        float2 y1 = *reinterpret_cast<const float2*>(yb + ((size_t)(1*Tx + tt) << 8));
        float2 y2 = *reinterpret_cast<const float2*>(yb + ((size_t)(2*Tx + tt) << 8));
        float2 y3 = *reinterpret_cast<const float2*>(yb + ((size_t)(3*Tx + tt) << 8));
        #pragma unroll
        for (int mi = 0; mi < TILE_M; mi++) {
            acc0[mi] = fmaf(wv[mi].x, y0.x, acc0[mi]);
            acc1[mi] = fmaf(wv[mi].x, y0.y, acc1[mi]);
            acc0[mi] = fmaf(wv[mi].y, y1.x, acc0[mi]);
            acc1[mi] = fmaf(wv[mi].y, y1.y, acc1[mi]);
            acc0[mi] = fmaf(wv[mi].z, y2.x, acc0[mi]);
            acc1[mi] = fmaf(wv[mi].z, y2.y, acc1[mi]);
            acc0[mi] = fmaf(wv[mi].w, y3.x, acc0[mi]);
            acc1[mi] = fmaf(wv[mi].w, y3.y, acc1[mi]);
        }
    }
    __syncthreads();

    // -------- phase 3: u = wh + proj1_b + wc@proj2_w + proj2_b --------
    {
        float2 b1 = *reinterpret_cast<const float2*>(p1b + o2);
        float2 b2 = *reinterpret_cast<const float2*>(p2b + o2);
        float2 pp[8];
        #pragma unroll
        for (int j = 0; j < 8; j++)
            pp[j] = *reinterpret_cast<const float2*>(p2w + j*Hx + o2);
        #pragma unroll
        for (int mi = 0; mi < TILE_M; mi++) {
            int m = m0 + mi;
            float u0 = 0.f, u1 = 0.f;
            if (m < mel_len) {
                u0 = acc0[mi] + b1.x + b2.x;
                u1 = acc1[mi] + b1.y + b2.y;
                #pragma unroll
                for (int j = 0; j < 8; j++) {
                    float wc = wc_sh[mi][j];
                    u0 = fmaf(wc, pp[j].x, u0);
                    u1 = fmaf(wc, pp[j].y, u1);
                }
            }
            u_sh[mi][o2]     = u0;
            u_sh[mi][o2 + 1] = u1;
        }
    }
    __syncthreads();

    // -------- phase 4: o = u @ projo_w + projo_b (thread owns 8 m x 4 adjacent j) ----
    int j4 = t << 2;   // 0..508
    float acc2[TILE_M][4];
    #pragma unroll
    for (int mi = 0; mi < TILE_M; mi++)
        #pragma unroll
        for (int r = 0; r < 4; r++) acc2[mi][r] = 0.f;

    #pragma unroll 4
    for (int h = 0; h < Hx; h++) {
        float4 pw = *reinterpret_cast<const float4*>(pow_ + (size_t)h*(2*Hx) + j4);
        #pragma unroll
        for (int mi = 0; mi < TILE_M; mi++) {
            float uv = u_sh[mi][h];
            acc2[mi][0] = fmaf(uv, pw.x, acc2[mi][0]);
            acc2[mi][1] = fmaf(uv, pw.y, acc2[mi][1]);
            acc2[mi][2] = fmaf(uv, pw.z, acc2[mi][2]);
            acc2[mi][3] = fmaf(uv, pw.w, acc2[mi][3]);
        }
    }
    float4 pb4 = *reinterpret_cast<const float4*>(pob + j4);
    #pragma unroll
    for (int mi = 0; mi < TILE_M; mi++) {
        int m = m0 + mi;
        float4 ov;
        ov.x = acc2[mi][0] + pb4.x;
        ov.y = acc2[mi][1] + pb4.y;
        ov.z = acc2[mi][2] + pb4.z;
        ov.w = acc2[mi][3] + pb4.w;
        *reinterpret_cast<float4*>(outO + (size_t)(b*Mx + m)*(2*Hx) + j4) = ov;
    }
}

// ------------------------- launch -------------------------
extern "C" void kernel_launch(void* const* d_in, const int* in_sizes, int n_in,
                              void* d_out, int out_size) {
    (void)in_sizes; (void)n_in; (void)out_size;
    const float* x        = (const float*)d_in[0];
    const float* xdur     = (const float*)d_in[2];
    const int*   xlens    = (const int*)  d_in[3];
    const float* proj_w   = (const float*)d_in[4];
    const float* proj_b   = (const float*)d_in[5];
    const float* conv_w   = (const float*)d_in[6];
    const float* conv_b   = (const float*)d_in[7];
    const float* conv_g   = (const float*)d_in[8];
    const float* conv_bt  = (const float*)d_in[9];
    const float* q_w1     = (const float*)d_in[10];
    const float* q_b1     = (const float*)d_in[11];
    const float* q_g      = (const float*)d_in[12];
    const float* q_bt     = (const float*)d_in[13];
    const float* q_w2     = (const float*)d_in[14];
    const float* q_b2     = (const float*)d_in[15];
    const float* p_w1     = (const float*)d_in[16];
    const float* p_b1     = (const float*)d_in[17];
    const float* p_g      = (const float*)d_in[18];
    const float* p_bt     = (const float*)d_in[19];
    const float* p_w2     = (const float*)d_in[20];
    const float* p_b2     = (const float*)d_in[21];
    const float* proj1_w  = (const float*)d_in[22];
    const float* proj1_b  = (const float*)d_in[23];
    const float* proj2_w  = (const float*)d_in[24];
    const float* proj2_b  = (const float*)d_in[25];
    const float* projo_w  = (const float*)d_in[26];
    const float* projo_b  = (const float*)d_in[27];

    float* out     = (float*)d_out;
    float* outO    = out;                                    // B*M*2H
    float* outMask = out + (size_t)Bx*Mx*2*Hx;               // B*M*T
    float* outLens = outMask + (size_t)Bx*Mx*Tx;             // B
    float* outW    = outLens + Bx;                           // B*Q*M*T

    kDur<<<Bx, 32>>>(xdur, outLens);
    dim3 ghy(Bx, 4, 5);
    kHY<<<ghy, 256>>>(x, proj_w, proj_b, proj1_w, xlens);
    kConv<<<Bx*Tx, Hx>>>(conv_w, conv_b, conv_g, conv_bt, xlens);
    kMain<<<Bx*NTILES, 128>>>(xlens,
        q_w1, q_b1, q_g, q_bt, q_w2, q_b2,
        p_w1, p_b1, p_g, p_bt, p_w2, p_b2,
        proj1_b, proj2_w, proj2_b, projo_w, projo_b,
        outO, outMask, outW);
}

// round 5
// speedup vs baseline: 1.1843x; 1.0854x over previous
#include <cuda_runtime.h>
#include <math.h>

#define Bx 32
#define Tx 128
#define Hx 256
#define Mx 1000
#define Qx 4
#define TILE_M 8
#define NTILES 125   // 1000 / 8

// ------------------------- device scratch -------------------------
__device__ float gH [Bx*Tx*Hx];            // h = (x@proj_w + b) * valid
__device__ float gHC[Bx*Tx*8];             // conv-block output
__device__ float gE [Bx*Tx];
__device__ float gS [Bx*Tx];
__device__ int   gML[Bx];
__device__ float gY [(size_t)Bx*Qx*Tx*Hx]; // Y[b,q,t,o]  (16 MB)

// ------------------------- kDur -------------------------
__global__ void kDur(const float* __restrict__ xdur, float* __restrict__ outLens) {
    int b = blockIdx.x;
    if (threadIdx.x == 0) {
        float run = 0.f;
        for (int t = 0; t < Tx; t++) {
            float d = xdur[b*Tx + t];
            gS[b*Tx + t] = run;
            run += d;
            gE[b*Tx + t] = run;
        }
        int ml = (int)rintf(run);
        if (ml > Mx) ml = Mx;
        gML[b] = ml;
        outLens[b] = (float)ml;
    }
}

// ------------------------- kHY: fused x@proj_w (seg 0) and x@proj1_w_q (segs 1-4) -----
// grid (Bx, 4 row-tiles, 5 segs); block 128.
// Block computes C[32 rows][256 cols]; thread tile 8 rows x 8 cols.
// rg = tid>>5 (0..3) -> rows rg*8..+7 ; oc = (tid&31)*8 -> 8 cols.
__global__ void __launch_bounds__(128) kHY(const float* __restrict__ x,
                                           const float* __restrict__ proj_w,
                                           const float* __restrict__ proj_b,
                                           const float* __restrict__ p1w,
                                           const int*   __restrict__ xlens) {
    __shared__ float xs[32][Hx];   // 32KB
    int b   = blockIdx.x;
    int t0  = blockIdx.y * 32;
    int seg = blockIdx.z;
    int tid = threadIdx.x;

    // cooperative load: 32 rows x 256 cols, 128 threads -> 64 float4 each
    {
        const float4* src = reinterpret_cast<const float4*>(x + (size_t)(b*Tx + t0)*Hx);
        float4* dst = reinterpret_cast<float4*>(&xs[0][0]);
        #pragma unroll
        for (int i = 0; i < 16; i++)
            dst[tid + i*128] = src[tid + i*128];
    }
    __syncthreads();

    const float* W = (seg == 0) ? proj_w : (p1w + (size_t)(seg-1)*Hx*Hx);
    int rg = tid >> 5;            // 0..3
    int oc = (tid & 31) << 3;     // 0..248
    int r0 = rg << 3;

    float acc[8][8];
    #pragma unroll
    for (int i = 0; i < 8; i++)
        #pragma unroll
        for (int j = 0; j < 8; j++) acc[i][j] = 0.f;

    #pragma unroll 2
    for (int h = 0; h < Hx; h++) {
        float4 wa = *reinterpret_cast<const float4*>(W + (size_t)h*Hx + oc);
        float4 wb = *reinterpret_cast<const float4*>(W + (size_t)h*Hx + oc + 4);
        #pragma unroll
        for (int i = 0; i < 8; i++) {
            float xv = xs[r0 + i][h];
            acc[i][0] = fmaf(xv, wa.x, acc[i][0]);
            acc[i][1] = fmaf(xv, wa.y, acc[i][1]);
            acc[i][2] = fmaf(xv, wa.z, acc[i][2]);
            acc[i][3] = fmaf(xv, wa.w, acc[i][3]);
            acc[i][4] = fmaf(xv, wb.x, acc[i][4]);
            acc[i][5] = fmaf(xv, wb.y, acc[i][5]);
            acc[i][6] = fmaf(xv, wb.z, acc[i][6]);
            acc[i][7] = fmaf(xv, wb.w, acc[i][7]);
        }
    }

    if (seg == 0) {
        int xlen = xlens[b];
        float4 pba = *reinterpret_cast<const float4*>(proj_b + oc);
        float4 pbb = *reinterpret_cast<const float4*>(proj_b + oc + 4);
        #pragma unroll
        for (int i = 0; i < 8; i++) {
            int row = t0 + r0 + i;
            float4 o1, o2;
            o1.x = acc[i][0]+pba.x; o1.y = acc[i][1]+pba.y; o1.z = acc[i][2]+pba.z; o1.w = acc[i][3]+pba.w;
            o2.x = acc[i][4]+pbb.x; o2.y = acc[i][5]+pbb.y; o2.z = acc[i][6]+pbb.z; o2.w = acc[i][7]+pbb.w;
            if (row >= xlen) { o1 = make_float4(0,0,0,0); o2 = make_float4(0,0,0,0); }
            float* dst = &gH[(size_t)(b*Tx + row)*Hx + oc];
            *reinterpret_cast<float4*>(dst)     = o1;
            *reinterpret_cast<float4*>(dst + 4) = o2;
        }
    } else {
        int q = seg - 1;
        #pragma unroll
        for (int i = 0; i < 8; i++) {
            int row = t0 + r0 + i;
            float* dst = &gY[(size_t)((b*Qx + q)*Tx + row)*Hx + oc];
            *reinterpret_cast<float4*>(dst)     = make_float4(acc[i][0], acc[i][1], acc[i][2], acc[i][3]);
            *reinterpret_cast<float4*>(dst + 4) = make_float4(acc[i][4], acc[i][5], acc[i][6], acc[i][7]);
        }
    }
}

// ------------------------- kConv: conv1d(k=3) + LN(8) + silu, *valid -------------------------
__global__ void __launch_bounds__(Hx) kConv(const float* __restrict__ cw,
                                            const float* __restrict__ cb,
                                            const float* __restrict__ cg,
                                            const float* __restrict__ cbeta,
                                            const int*   __restrict__ xlens) {
    int bt = blockIdx.x;
    int b = bt >> 7, t = bt & 127;
    int cin = threadIdx.x;

    float hm = (t > 0)   ? gH[(size_t)(bt-1)*Hx + cin] : 0.f;
    float h0 =             gH[(size_t) bt   *Hx + cin];
    float hp = (t < 127) ? gH[(size_t)(bt+1)*Hx + cin] : 0.f;

    float loc[8];
    #pragma unroll
    for (int c = 0; c < 8; c++) {
        const float* w = cw + c*(Hx*3) + cin*3;
        loc[c] = fmaf(w[0], hm, fmaf(w[1], h0, w[2]*hp));
    }
    #pragma unroll
    for (int off = 16; off > 0; off >>= 1) {
        #pragma unroll
        for (int c = 0; c < 8; c++)
            loc[c] += __shfl_xor_sync(0xffffffffu, loc[c], off);
    }
    __shared__ float red[8][8];
    __shared__ float tmp8[8];
    int warp = cin >> 5, lane = cin & 31;
    if (lane == 0) {
        #pragma unroll
        for (int c = 0; c < 8; c++) red[warp][c] = loc[c];
    }
    __syncthreads();
    if (cin < 8) {
        float v = cb[cin];
        #pragma unroll
        for (int w = 0; w < 8; w++) v += red[w][cin];
        tmp8[cin] = v;
    }
    __syncthreads();
    if (cin < 8) {
        float mu = 0.f;
        #pragma unroll
        for (int j = 0; j < 8; j++) mu += tmp8[j];
        mu *= 0.125f;
        float var = 0.f;
        #pragma unroll
        for (int j = 0; j < 8; j++) { float d = tmp8[j]-mu; var = fmaf(d, d, var); }
        var *= 0.125f;
        float zn = (tmp8[cin]-mu) * rsqrtf(var + 1e-5f) * cg[cin] + cbeta[cin];
        float sil = zn / (1.f + expf(-zn));
        gHC[bt*8 + cin] = (t < xlens[b]) ? sil : 0.f;
    }
}

// ------------------------- kMain -------------------------
__global__ void __launch_bounds__(128) kMain(
    const int*   __restrict__ xlens,
    const float* __restrict__ qw1, const float* __restrict__ qb1,
    const float* __restrict__ qg,  const float* __restrict__ qbeta,
    const float* __restrict__ qw2, const float* __restrict__ qb2,
    const float* __restrict__ pw1, const float* __restrict__ pb1,
    const float* __restrict__ pg,  const float* __restrict__ pbeta,
    const float* __restrict__ pw2, const float* __restrict__ pb2,
    const float* __restrict__ p1b, const float* __restrict__ p2w,
    const float* __restrict__ p2b, const float* __restrict__ pow_,
    const float* __restrict__ pob,
    float* __restrict__ outO, float* __restrict__ outMask,
    float* __restrict__ outW)
{
    __shared__ float w_sh[TILE_M][Tx][4];   // 16KB; u_sh aliases the front 8KB after phase 2
    __shared__ float wc_sh[TILE_M][8];
    __shared__ float redA[4][4];
    __shared__ float redB[4][4];
    __shared__ float redC[4][8];

    // interleaved grid: padded tiles spread across waves
    int b    = blockIdx.x % Bx;
    int tile = blockIdx.x / Bx;
    int m0   = tile * TILE_M;
    int t    = threadIdx.x;
    int warp = t >> 5, lane = t & 31;
    int mel_len = gML[b];
    int xlen    = xlens[b];

    // -------- fully padded tile fast path --------
    if (m0 >= mel_len) {
        int j4 = t << 2;
        float4 pb4 = *reinterpret_cast<const float4*>(pob + j4);
        #pragma unroll
        for (int mi = 0; mi < TILE_M; mi++) {
            int m = m0 + mi;
            outMask[(size_t)(b*Mx + m)*Tx + t] = 1.f;
            #pragma unroll
            for (int q = 0; q < 4; q++)
                outW[((size_t)(b*Qx + q)*Mx + m)*Tx + t] = 0.f;
            *reinterpret_cast<float4*>(outO + (size_t)(b*Mx + m)*(2*Hx) + j4) = pb4;
        }
        return;
    }

    bool tmask = (t >= xlen);
    float fh[8];
    #pragma unroll
    for (int c = 0; c < 8; c++) fh[c] = gHC[(b*Tx + t)*8 + c];
    float se = gE[b*Tx + t], ss = gS[b*Tx + t];

    // m-independent parts of the two tiny MLPs
    float zqb[4];
    #pragma unroll
    for (int q = 0; q < 4; q++) zqb[q] = qb1[q];
    #pragma unroll
    for (int i = 0; i < 8; i++) {
        #pragma unroll
        for (int q = 0; q < 4; q++) zqb[q] = fmaf(fh[i], qw1[i*4 + q], zqb[q]);
    }
    float zpb0 = pb1[0], zpb1 = pb1[1];
    #pragma unroll
    for (int i = 0; i < 8; i++) {
        zpb0 = fmaf(fh[i], pw1[i*2 + 0], zpb0);
        zpb1 = fmaf(fh[i], pw1[i*2 + 1], zpb1);
    }

    // -------- phase 1: per-m scores, softmax, wc --------
    for (int mi = 0; mi < TILE_M; mi++) {
        int m = m0 + mi;
        bool pad = (m >= mel_len);
        outMask[(size_t)(b*Mx + m)*Tx + t] = pad ? 1.f : 0.f;
        if (pad) {
            #pragma unroll
            for (int q = 0; q < 4; q++) {
                w_sh[mi][t][q] = 0.f;
                outW[((size_t)(b*Qx + q)*Mx + m)*Tx + t] = 0.f;
            }
            if (t < 8) wc_sh[mi][t] = 0.f;
            continue;
        }
        float tf = (float)(m + 1);
        float f8 = tmask ? 0.f : (tf - ss);
        float f9 = tmask ? 0.f : (se - tf);

        // q-MLP
        float z[4];
        #pragma unroll
        for (int q = 0; q < 4; q++)
            z[q] = fmaf(f9, qw1[36 + q], fmaf(f8, qw1[32 + q], zqb[q]));
        float mu = 0.25f * (z[0] + z[1] + z[2] + z[3]);
        float var = 0.f;
        #pragma unroll
        for (int q = 0; q < 4; q++) { float d = z[q]-mu; var = fmaf(d, d, var); }
        var *= 0.25f;
        float rinv = rsqrtf(var + 1e-5f);
        float a[4];
        #pragma unroll
        for (int q = 0; q < 4; q++) {
            float zn = (z[q]-mu) * rinv * qg[q] + qbeta[q];
            a[q] = zn / (1.f + expf(-zn));
        }
        float sc[4];
        #pragma unroll
        for (int q = 0; q < 4; q++) {
            float s = qb2[q];
            #pragma unroll
            for (int j = 0; j < 4; j++) s = fmaf(a[j], qw2[j*4 + q], s);
            sc[q] = tmask ? -1e30f : s;
        }

        // p-MLP
        float zp0 = fmaf(f9, pw1[18], fmaf(f8, pw1[16], zpb0));
        float zp1 = fmaf(f9, pw1[19], fmaf(f8, pw1[17], zpb1));
        float mup  = 0.5f * (zp0 + zp1);
        float d0 = zp0 - mup, d1 = zp1 - mup;
        float varp = 0.5f * (d0*d0 + d1*d1);
        float rp = rsqrtf(varp + 1e-5f);
        float a0 = d0 * rp * pg[0] + pbeta[0];
        float a1 = d1 * rp * pg[1] + pbeta[1];
        a0 = a0 / (1.f + expf(-a0));
        a1 = a1 / (1.f + expf(-a1));
        float c0 = fmaf(a1, pw2[2], fmaf(a0, pw2[0], pb2[0]));
        float c1 = fmaf(a1, pw2[3], fmaf(a0, pw2[1], pb2[1]));

        // block softmax over t, 4 q's at once
        float v[4];
        #pragma unroll
        for (int q = 0; q < 4; q++) v[q] = sc[q];
        #pragma unroll
        for (int off = 16; off > 0; off >>= 1) {
            #pragma unroll
            for (int q = 0; q < 4; q++)
                v[q] = fmaxf(v[q], __shfl_xor_sync(0xffffffffu, v[q], off));
        }
        if (lane == 0) {
            #pragma unroll
            for (int q = 0; q < 4; q++) redA[warp][q] = v[q];
        }
        __syncthreads();
        float mx[4];
        #pragma unroll
        for (int q = 0; q < 4; q++)
            mx[q] = fmaxf(fmaxf(redA[0][q], redA[1][q]), fmaxf(redA[2][q], redA[3][q]));
        float ex[4];
        #pragma unroll
        for (int q = 0; q < 4; q++) {
            ex[q] = tmask ? 0.f : expf(sc[q] - mx[q]);
            v[q] = ex[q];
        }
        #pragma unroll
        for (int off = 16; off > 0; off >>= 1) {
            #pragma unroll
            for (int q = 0; q < 4; q++)
                v[q] += __shfl_xor_sync(0xffffffffu, v[q], off);
        }
        if (lane == 0) {
            #pragma unroll
            for (int q = 0; q < 4; q++) redB[warp][q] = v[q];
        }
        __syncthreads();
        float wgt[4];
        #pragma unroll
        for (int q = 0; q < 4; q++) {
            float sm = redB[0][q] + redB[1][q] + redB[2][q] + redB[3][q];
            wgt[q] = ex[q] / sm;
            w_sh[mi][t][q] = wgt[q];
            outW[((size_t)(b*Qx + q)*Mx + m)*Tx + t] = wgt[q];
        }
        // wc: 8 block reductions of w[q]*c[p]
        float vv[8];
        #pragma unroll
        for (int q = 0; q < 4; q++) { vv[q*2] = wgt[q]*c0; vv[q*2+1] = wgt[q]*c1; }
        #pragma unroll
        for (int off = 16; off > 0; off >>= 1) {
            #pragma unroll
            for (int k = 0; k < 8; k++)
                vv[k] += __shfl_xor_sync(0xffffffffu, vv[k], off);
        }
        if (lane == 0) {
            #pragma unroll
            for (int k = 0; k < 8; k++) redC[warp][k] = vv[k];
        }
        __syncthreads();
        if (t < 8) wc_sh[mi][t] = redC[0][t] + redC[1][t] + redC[2][t] + redC[3][t];
    }
    __syncthreads();

    // -------- phase 2: wh accumulate (thread owns 8 m x 2 adjacent o) --------
    int o2 = t << 1;   // 0..254
    float acc0[TILE_M], acc1[TILE_M];
    #pragma unroll
    for (int mi = 0; mi < TILE_M; mi++) { acc0[mi] = 0.f; acc1[mi] = 0.f; }

    const float* yb = gY + (size_t)b*Qx*Tx*Hx + o2;
    // double-buffered prefetch of Y rows
    float2 ya[4], ybuf[4];
    #pragma unroll
    for (int q = 0; q < 4; q++)
        ya[q] = *reinterpret_cast<const float2*>(yb + ((size_t)(q*Tx + 0) << 8));
    for (int tt = 0; tt < xlen; tt++) {
        if (tt + 1 < xlen) {
            #pragma unroll
            for (int q = 0; q < 4; q++)
                ybuf[q] = *reinterpret_cast<const float2*>(yb + ((size_t)(q*Tx + tt + 1) << 8));
        }
        float4 wv[TILE_M];
        #pragma unroll
        for (int mi = 0; mi < TILE_M; mi++)
            wv[mi] = *reinterpret_cast<const float4*>(&w_sh[mi][tt][0]);
        #pragma unroll
        for (int mi = 0; mi < TILE_M; mi++) {
            acc0[mi] = fmaf(wv[mi].x, ya[0].x, acc0[mi]);
            acc1[mi] = fmaf(wv[mi].x, ya[0].y, acc1[mi]);
            acc0[mi] = fmaf(wv[mi].y, ya[1].x, acc0[mi]);
            acc1[mi] = fmaf(wv[mi].y, ya[1].y, acc1[mi]);
            acc0[mi] = fmaf(wv[mi].z, ya[2].x, acc0[mi]);
            acc1[mi] = fmaf(wv[mi].z, ya[2].y, acc1[mi]);
            acc0[mi] = fmaf(wv[mi].w, ya[3].x, acc0[mi]);
            acc1[mi] = fmaf(wv[mi].w, ya[3].y, acc1[mi]);
        }
        #pragma unroll
        for (int q = 0; q < 4; q++) ya[q] = ybuf[q];
    }
    __syncthreads();   // all w_sh reads done; pool reused as u_sh below

    float (*u_sh)[Hx] = reinterpret_cast<float(*)[Hx]>(&w_sh[0][0][0]);   // 8KB alias

    // -------- phase 3: u = wh + proj1_b + wc@proj2_w + proj2_b --------
    {
        float2 b1 = *reinterpret_cast<const float2*>(p1b + o2);
        float2 b2 = *reinterpret_cast<const float2*>(p2b + o2);
        float2 pp[8];
        #pragma unroll
        for (int j = 0; j < 8; j++)
            pp[j] = *reinterpret_cast<const float2*>(p2w + j*Hx + o2);
        #pragma unroll
        for (int mi = 0; mi < TILE_M; mi++) {
            int m = m0 + mi;
            float u0 = 0.f, u1 = 0.f;
            if (m < mel_len) {
                u0 = acc0[mi] + b1.x + b2.x;
                u1 = acc1[mi] + b1.y + b2.y;
                #pragma unroll
                for (int j = 0; j < 8; j++) {
                    float wc = wc_sh[mi][j];
                    u0 = fmaf(wc, pp[j].x, u0);
                    u1 = fmaf(wc, pp[j].y, u1);
                }
            }
            u_sh[mi][o2]     = u0;
            u_sh[mi][o2 + 1] = u1;
        }
    }
    __syncthreads();

    // -------- phase 4: o = u @ projo_w + projo_b (thread owns 8 m x 4 adjacent j) ----
    int j4 = t << 2;   // 0..508
    float acc2[TILE_M][4];
    #pragma unroll
    for (int mi = 0; mi < TILE_M; mi++)
        #pragma unroll
        for (int r = 0; r < 4; r++) acc2[mi][r] = 0.f;

    #pragma unroll 4
    for (int h = 0; h < Hx; h++) {
        float4 pw = *reinterpret_cast<const float4*>(pow_ + (size_t)h*(2*Hx) + j4);
        #pragma unroll
        for (int mi = 0; mi < TILE_M; mi++) {
            float uv = u_sh[mi][h];
            acc2[mi][0] = fmaf(uv, pw.x, acc2[mi][0]);
            acc2[mi][1] = fmaf(uv, pw.y, acc2[mi][1]);
            acc2[mi][2] = fmaf(uv, pw.z, acc2[mi][2]);
            acc2[mi][3] = fmaf(uv, pw.w, acc2[mi][3]);
        }
    }
    float4 pb4 = *reinterpret_cast<const float4*>(pob + j4);
    #pragma unroll
    for (int mi = 0; mi < TILE_M; mi++) {
        int m = m0 + mi;
        float4 ov;
        ov.x = acc2[mi][0] + pb4.x;
        ov.y = acc2[mi][1] + pb4.y;
        ov.z = acc2[mi][2] + pb4.z;
        ov.w = acc2[mi][3] + pb4.w;
        *reinterpret_cast<float4*>(outO + (size_t)(b*Mx + m)*(2*Hx) + j4) = ov;
    }
}

// ------------------------- launch -------------------------
extern "C" void kernel_launch(void* const* d_in, const int* in_sizes, int n_in,
                              void* d_out, int out_size) {
    (void)in_sizes; (void)n_in; (void)out_size;
    const float* x        = (const float*)d_in[0];
    const float* xdur     = (const float*)d_in[2];
    const int*   xlens    = (const int*)  d_in[3];
    const float* proj_w   = (const float*)d_in[4];
    const float* proj_b   = (const float*)d_in[5];
    const float* conv_w   = (const float*)d_in[6];
    const float* conv_b   = (const float*)d_in[7];
    const float* conv_g   = (const float*)d_in[8];
    const float* conv_bt  = (const float*)d_in[9];
    const float* q_w1     = (const float*)d_in[10];
    const float* q_b1     = (const float*)d_in[11];
    const float* q_g      = (const float*)d_in[12];
    const float* q_bt     = (const float*)d_in[13];
    const float* q_w2     = (const float*)d_in[14];
    const float* q_b2     = (const float*)d_in[15];
    const float* p_w1     = (const float*)d_in[16];
    const float* p_b1     = (const float*)d_in[17];
    const float* p_g      = (const float*)d_in[18];
    const float* p_bt     = (const float*)d_in[19];
    const float* p_w2     = (const float*)d_in[20];
    const float* p_b2     = (const float*)d_in[21];
    const float* proj1_w  = (const float*)d_in[22];
    const float* proj1_b  = (const float*)d_in[23];
    const float* proj2_w  = (const float*)d_in[24];
    const float* proj2_b  = (const float*)d_in[25];
    const float* projo_w  = (const float*)d_in[26];
    const float* projo_b  = (const float*)d_in[27];

    float* out     = (float*)d_out;
    float* outO    = out;                                    // B*M*2H
    float* outMask = out + (size_t)Bx*Mx*2*Hx;               // B*M*T
    float* outLens = outMask + (size_t)Bx*Mx*Tx;             // B
    float* outW    = outLens + Bx;                           // B*Q*M*T

    kDur<<<Bx, 32>>>(xdur, outLens);
    dim3 ghy(Bx, 4, 5);
    kHY<<<ghy, 128>>>(x, proj_w, proj_b, proj1_w, xlens);
    kConv<<<Bx*Tx, Hx>>>(conv_w, conv_b, conv_g, conv_bt, xlens);
    kMain<<<Bx*NTILES, 128>>>(xlens,
        q_w1, q_b1, q_g, q_bt, q_w2, q_b2,
        p_w1, p_b1, p_g, p_bt, p_w2, p_b2,
        proj1_b, proj2_w, proj2_b, projo_w, projo_b,
        outO, outMask, outW);
}